// round 5
// baseline (speedup 1.0000x reference)
#include <cuda_runtime.h>
#include <cuda_bf16.h>
#include <cstdint>

// Capsule routing: B=2048, R=64, H=512, NUM_ITER=3.  Output final_vec [B,H] f32.
//
// R5: persistent pipeline with a 6-slot x 32KB TMA chunk ring (192KB smem).
// 148 CTAs x 1024 threads; each CTA handles ~14 batches. A batch = 4 chunks
// (16 rows each). After batch i's LDS-consumption sync, its 4 ring slots free
// and thread 0 tops the TMA queue up to chunk 4i+9 (next batch + half of the
// one after). The TMA engine therefore never idles at batch boundaries,
// unlike R4 where it only ran during the compute window (83% duty).

#define B_DIM 2048
#define R_DIM 64
#define H_DIM 512
#define NT 1024
#define R_HALF 32
#define GRID 148
#define NSLOT 6
#define CHUNK_ROWS 16
#define CHUNK_FLOATS (CHUNK_ROWS * H_DIM)      // 8192
#define CHUNK_BYTES  (CHUNK_FLOATS * 4)        // 32768

__device__ __forceinline__ float fast_exp2(float x) {
    float r;
    asm("ex2.approx.ftz.f32 %0, %1;" : "=f"(r) : "f"(x));
    return r;
}

// Block-wide sum over 1024 threads (32 warps); result broadcast to all.
__device__ __forceinline__ float block_sum(float val, float* sred) {
    #pragma unroll
    for (int o = 16; o > 0; o >>= 1)
        val += __shfl_xor_sync(0xffffffffu, val, o);
    int wid = threadIdx.x >> 5;
    int lid = threadIdx.x & 31;
    __syncthreads();
    if (lid == 0) sred[wid] = val;
    __syncthreads();
    if (threadIdx.x < 32) {
        float v = sred[lid];
        #pragma unroll
        for (int o = 16; o > 0; o >>= 1)
            v += __shfl_xor_sync(0xffffffffu, v, o);
        if (lid == 0) sred[0] = v;
    }
    __syncthreads();
    return sred[0];
}

__device__ __forceinline__ void mbar_wait_acq(uint32_t mbar, uint32_t parity) {
    asm volatile(
        "{\n\t"
        ".reg .pred P;\n\t"
        "WAIT_LOOP_%=:\n\t"
        "mbarrier.try_wait.parity.acquire.cta.shared::cta.b64 P, [%0], %1, 0x989680;\n\t"
        "@P bra.uni WAIT_DONE_%=;\n\t"
        "bra.uni WAIT_LOOP_%=;\n\t"
        "WAIT_DONE_%=:\n\t"
        "}"
        :: "r"(mbar), "r"(parity) : "memory");
}

__global__ void __launch_bounds__(NT, 1)
capsule_kernel(const float* __restrict__ x, float* __restrict__ out) {
    extern __shared__ float sbuf[];            // NSLOT * CHUNK_FLOATS = 192KB
    __shared__ float sh_a[NT];
    __shared__ float sh_b[NT];
    __shared__ float sh_c[NT];
    __shared__ float sred[32];
    __shared__ uint64_t mbars[NSLOT];

    const uint32_t mbar0 = (uint32_t)__cvta_generic_to_shared(mbars);
    const uint32_t sbuf_addr = (uint32_t)__cvta_generic_to_shared(sbuf);

    const int tid  = threadIdx.x;
    const int h    = tid & (H_DIM - 1);
    const int half = tid >> 9;                 // 0/1: row half (rows 0-31 / 32-63)
    const int prt  = tid ^ H_DIM;              // partner thread
    const int bid  = blockIdx.x;

    if (tid < NSLOT) {
        uint32_t mb = mbar0 + 8u * tid;
        asm volatile("mbarrier.init.shared.b64 [%0], %1;" :: "r"(mb), "r"(1));
    }
    asm volatile("fence.proxy.async.shared::cta;" ::: "memory");
    __syncthreads();

    const int nbat = (B_DIM - bid + GRID - 1) / GRID;   // batches for this CTA
    const int total_chunks = 4 * nbat;

    // Chunk issue helper (thread 0 only, inlined via lambda-style macro logic).
    // global-local chunk index g: batch_local = g>>2, j = g&3, slot = g%NSLOT.
    int cursor = 0;
    if (tid == 0) {
        int lim = total_chunks < NSLOT ? total_chunks : NSLOT;
        for (; cursor < lim; cursor++) {
            int g = cursor;
            int slot = g % NSLOT;
            int gb = bid + (g >> 2) * GRID;
            const char* src = (const char*)(x + (size_t)gb * (R_DIM * H_DIM)
                                              + (size_t)(g & 3) * CHUNK_FLOATS);
            uint32_t mb = mbar0 + 8u * slot;
            asm volatile("mbarrier.arrive.expect_tx.shared.b64 _, [%0], %1;"
                         :: "r"(mb), "r"(CHUNK_BYTES));
            asm volatile(
                "cp.async.bulk.shared::cta.global.mbarrier::complete_tx::bytes "
                "[%0], [%1], %2, [%3];"
                :: "r"(sbuf_addr + (uint32_t)slot * CHUNK_BYTES), "l"(src),
                   "r"(CHUNK_BYTES), "r"(mb) : "memory");
        }
    }

    const float L2E = 1.4426950408889634f;

    for (int i = 0; i < nbat; i++) {
        const int b = bid + i * GRID;

        // This thread reads chunks j0=2*half, j0+1 of batch i.
        const int g0 = 4 * i + 2 * half;
        const int g1 = g0 + 1;
        const int s0 = g0 % NSLOT;
        const int s1 = g1 % NSLOT;
        mbar_wait_acq(mbar0 + 8u * s0, (uint32_t)((g0 / NSLOT) & 1));
        mbar_wait_acq(mbar0 + 8u * s1, (uint32_t)((g1 / NSLOT) & 1));

        // ---- smem -> registers, fused partial sum/max/min ----
        float xr[R_HALF];
        float psum = 0.0f;
        float pmax = -3.402823466e38f;
        float pmin =  3.402823466e38f;
        const float* c0 = sbuf + (size_t)s0 * CHUNK_FLOATS + h;
        const float* c1 = sbuf + (size_t)s1 * CHUNK_FLOATS + h;
        #pragma unroll
        for (int r = 0; r < CHUNK_ROWS; r++) {
            xr[r] = c0[r * H_DIM];
            xr[r + CHUNK_ROWS] = c1[r * H_DIM];
        }
        #pragma unroll
        for (int r = 0; r < R_HALF; r++) {
            psum += xr[r];
            pmax = fmaxf(pmax, xr[r]);
            pmin = fminf(pmin, xr[r]);
        }
        sh_a[tid] = psum;
        sh_b[tid] = pmax;
        sh_c[tid] = pmin;
        __syncthreads();   // ALL 4 chunks of batch i consumed by everyone here

        // Top up the TMA queue: safe to issue g while g-NSLOT is consumed,
        // i.e. up to 4*i+3 + NSLOT.
        if (tid == 0) {
            int lim = 4 * i + 3 + NSLOT;
            if (lim >= total_chunks) lim = total_chunks - 1;
            for (; cursor <= lim; cursor++) {
                int g = cursor;
                int slot = g % NSLOT;
                int gb = bid + (g >> 2) * GRID;
                const char* src = (const char*)(x + (size_t)gb * (R_DIM * H_DIM)
                                                  + (size_t)(g & 3) * CHUNK_FLOATS);
                uint32_t mb = mbar0 + 8u * slot;
                asm volatile("mbarrier.arrive.expect_tx.shared.b64 _, [%0], %1;"
                             :: "r"(mb), "r"(CHUNK_BYTES));
                asm volatile(
                    "cp.async.bulk.shared::cta.global.mbarrier::complete_tx::bytes "
                    "[%0], [%1], %2, [%3];"
                    :: "r"(sbuf_addr + (uint32_t)slot * CHUNK_BYTES), "l"(src),
                       "r"(CHUNK_BYTES), "r"(mb) : "memory");
            }
        }

        const float sum0 = psum + sh_a[prt];
        const float xmax = fmaxf(pmax, sh_b[prt]);
        const float xmin = fminf(pmin, sh_c[prt]);

        // ---- iter 0: uniform coefficients -> mean over r, squash ----
        float s = sum0 * (1.0f / (float)R_DIM);
        float norm = block_sum(0.5f * s * s, sred);
        float sq = sqrtf(norm);
        float f  = sq / (1.0f + sq);
        float v  = f * s;
        float w  = v;

        // ---- iterations 1 and 2 ----
        #pragma unroll
        for (int it = 0; it < 2; it++) {
            float wl = w * L2E;
            float m  = fmaxf(wl * xmax, wl * xmin);
            float pse  = 0.0f;
            float psex = 0.0f;
            #pragma unroll
            for (int r = 0; r < R_HALF; r++) {
                float e = fast_exp2(fmaf(xr[r], wl, -m));
                pse += e;
                psex = fmaf(e, xr[r], psex);
            }
            sh_a[tid] = pse;    // last sh_a read was before block_sum's sync
            sh_b[tid] = psex;
            __syncthreads();
            float se  = pse  + sh_a[prt];
            float sex = psex + sh_b[prt];
            s = sex / se;

            norm = block_sum(0.5f * s * s, sred);
            sq = sqrtf(norm);
            f  = sq / (1.0f + sq);
            v  = f * s;
            w += v;
        }

        if (half == 0)
            out[(size_t)b * H_DIM + h] = v;
    }
}

extern "C" void kernel_launch(void* const* d_in, const int* in_sizes, int n_in,
                              void* d_out, int out_size) {
    const float* x = (const float*)d_in[0];
    float* out = (float*)d_out;
    cudaFuncSetAttribute(capsule_kernel,
                         cudaFuncAttributeMaxDynamicSharedMemorySize,
                         NSLOT * CHUNK_BYTES);
    capsule_kernel<<<GRID, NT, NSLOT * CHUNK_BYTES>>>(x, out);
}

// round 6
// speedup vs baseline: 1.1769x; 1.1769x over previous
#include <cuda_runtime.h>
#include <cuda_bf16.h>
#include <cstdint>

// Capsule routing: B=2048, R=64, H=512, NUM_ITER=3.  Output final_vec [B,H] f32.
//
// R6: 512 threads/CTA, each thread owns one FULL h-column (64 rows in regs).
// Eliminates all partner exchanges of R4/R5 (xmax/xmin/sums are thread-local);
// block-wide coupling is only the squash norm -> 3 single-barrier block_sums.
// 4 CTA barriers per batch total (vs ~13 in R4). Persistent 148 CTAs, TMA
// 7-slot x 32KB chunk ring (224KB smem) keeps the copy engine >=1 batch ahead;
// chunk waits are elected (tid<4) and folded into one barrier.

#define B_DIM 2048
#define R_DIM 64
#define H_DIM 512
#define NT 512
#define GRID 148
#define NSLOT 7
#define CHUNK_ROWS 16
#define CHUNK_FLOATS (CHUNK_ROWS * H_DIM)      // 8192
#define CHUNK_BYTES  (CHUNK_FLOATS * 4)        // 32768

__device__ __forceinline__ float fast_exp2(float x) {
    float r;
    asm("ex2.approx.ftz.f32 %0, %1;" : "=f"(r) : "f"(x));
    return r;
}

__device__ __forceinline__ void mbar_wait_acq(uint32_t mbar, uint32_t parity) {
    asm volatile(
        "{\n\t"
        ".reg .pred P;\n\t"
        "WAIT_LOOP_%=:\n\t"
        "mbarrier.try_wait.parity.acquire.cta.shared::cta.b64 P, [%0], %1, 0x989680;\n\t"
        "@P bra.uni WAIT_DONE_%=;\n\t"
        "bra.uni WAIT_LOOP_%=;\n\t"
        "WAIT_DONE_%=:\n\t"
        "}"
        :: "r"(mbar), "r"(parity) : "memory");
}

__device__ __forceinline__ void tma_chunk(uint32_t dst, const char* src,
                                          uint32_t mb) {
    asm volatile("mbarrier.arrive.expect_tx.shared.b64 _, [%0], %1;"
                 :: "r"(mb), "r"(CHUNK_BYTES));
    asm volatile(
        "cp.async.bulk.shared::cta.global.mbarrier::complete_tx::bytes "
        "[%0], [%1], %2, [%3];"
        :: "r"(dst), "l"(src), "r"(CHUNK_BYTES), "r"(mb) : "memory");
}

// Single-barrier block sum over 512 threads (16 warps). Caller passes a
// DISTINCT sred buffer (16 floats) per call site to avoid reuse hazards.
__device__ __forceinline__ float block_sum16(float val, volatile float* sred) {
    #pragma unroll
    for (int o = 16; o > 0; o >>= 1)
        val += __shfl_xor_sync(0xffffffffu, val, o);
    const int wid = threadIdx.x >> 5;
    const int lid = threadIdx.x & 31;
    if (lid == 0) sred[wid] = val;
    __syncthreads();
    float v = sred[lid & 15];
    #pragma unroll
    for (int o = 8; o > 0; o >>= 1)
        v += __shfl_xor_sync(0xffffffffu, v, o);
    return v;
}

__global__ void __launch_bounds__(NT, 1)
capsule_kernel(const float* __restrict__ x, float* __restrict__ out) {
    extern __shared__ float sbuf[];            // NSLOT * 32KB = 224KB ring
    __shared__ float sred0[16], sred1[16], sred2[16];
    __shared__ uint64_t mbars[NSLOT];

    const uint32_t mbar0 = (uint32_t)__cvta_generic_to_shared(mbars);
    const uint32_t sbuf_addr = (uint32_t)__cvta_generic_to_shared(sbuf);

    const int tid = threadIdx.x;               // == h column
    const int bid = blockIdx.x;
    const int wid = tid >> 5;
    const int lid = tid & 31;

    if (tid < NSLOT)
        asm volatile("mbarrier.init.shared.b64 [%0], %1;"
                     :: "r"(mbar0 + 8u * tid), "r"(1));
    asm volatile("fence.proxy.async.shared::cta;" ::: "memory");
    __syncthreads();

    const int nbat = (B_DIM - bid + GRID - 1) / GRID;
    const int total_chunks = 4 * nbat;

    // Prime the ring.
    int cursor = 0;
    if (tid == 0) {
        int lim = total_chunks < NSLOT ? total_chunks : NSLOT;
        for (; cursor < lim; cursor++) {
            int g = cursor;
            int gb = bid + (g >> 2) * GRID;
            const char* src = (const char*)(x + (size_t)gb * (R_DIM * H_DIM)
                                              + (size_t)(g & 3) * CHUNK_FLOATS);
            tma_chunk(sbuf_addr + (uint32_t)(g % NSLOT) * CHUNK_BYTES, src,
                      mbar0 + 8u * (g % NSLOT));
        }
    }

    const float L2E = 1.4426950408889634f;

    for (int i = 0; i < nbat; i++) {
        const int b = bid + i * GRID;

        // Elected waits for this batch's 4 chunks, then one barrier.
        if (tid < 4) {
            int g = 4 * i + tid;
            mbar_wait_acq(mbar0 + 8u * (g % NSLOT), (uint32_t)((g / NSLOT) & 1));
        }
        __syncthreads();                        // barrier #1

        // ---- smem -> registers (full column), fused sum/max/min ----
        float xr[R_DIM];
        float sum0 = 0.0f;
        float xmax = -3.402823466e38f;
        float xmin =  3.402823466e38f;
        #pragma unroll
        for (int c = 0; c < 4; c++) {
            const float* cp = sbuf + (size_t)((4 * i + c) % NSLOT) * CHUNK_FLOATS + tid;
            #pragma unroll
            for (int r = 0; r < CHUNK_ROWS; r++) {
                float xv = cp[r * H_DIM];
                xr[c * CHUNK_ROWS + r] = xv;
                sum0 += xv;
                xmax = fmaxf(xmax, xv);
                xmin = fminf(xmin, xv);
            }
        }

        // ---- iter 0: mean over r, squash (block_sum #1, barrier #2) ----
        float s = sum0 * (1.0f / (float)R_DIM);
        {   // inline block_sum16 so the refill lands right after its barrier
            float val = s * s;
            #pragma unroll
            for (int o = 16; o > 0; o >>= 1)
                val += __shfl_xor_sync(0xffffffffu, val, o);
            if (lid == 0) sred0[wid] = val;
            __syncthreads();                    // = consumption point for batch i
            // Refill the ring: slots of batch i are now free.
            if (tid == 0) {
                int lim = 4 * i + 3 + NSLOT;
                if (lim >= total_chunks) lim = total_chunks - 1;
                for (; cursor <= lim; cursor++) {
                    int g = cursor;
                    int gb = bid + (g >> 2) * GRID;
                    const char* src = (const char*)(x + (size_t)gb * (R_DIM * H_DIM)
                                                      + (size_t)(g & 3) * CHUNK_FLOATS);
                    tma_chunk(sbuf_addr + (uint32_t)(g % NSLOT) * CHUNK_BYTES, src,
                              mbar0 + 8u * (g % NSLOT));
                }
            }
            float v16 = sred0[lid & 15];
            #pragma unroll
            for (int o = 8; o > 0; o >>= 1)
                v16 += __shfl_xor_sync(0xffffffffu, v16, o);
            s = s; // keep s
            float sq = sqrtf(v16);
            float f  = sq / (1.0f + sq);
            // fallthrough with v,w below
            float v = f * s;
            float w = v;

            // ---- iterations 1 and 2 ----
            #pragma unroll
            for (int it = 0; it < 2; it++) {
                float wl = w * L2E;
                float m  = fmaxf(wl * xmax, wl * xmin);
                float se  = 0.0f;
                float sex = 0.0f;
                #pragma unroll
                for (int r = 0; r < R_DIM; r++) {
                    float e = fast_exp2(fmaf(xr[r], wl, -m));
                    se += e;
                    sex = fmaf(e, xr[r], sex);
                }
                float s2 = sex / se;

                float norm = block_sum16(s2 * s2, it == 0 ? sred1 : sred2); // barriers #3,#4
                float sq2 = sqrtf(norm);
                float f2  = sq2 / (1.0f + sq2);
                v = f2 * s2;
                w += v;
            }

            out[(size_t)b * H_DIM + tid] = v;
        }
    }
}

extern "C" void kernel_launch(void* const* d_in, const int* in_sizes, int n_in,
                              void* d_out, int out_size) {
    const float* x = (const float*)d_in[0];
    float* out = (float*)d_out;
    cudaFuncSetAttribute(capsule_kernel,
                         cudaFuncAttributeMaxDynamicSharedMemorySize,
                         NSLOT * CHUNK_BYTES);
    capsule_kernel<<<GRID, NT, NSLOT * CHUNK_BYTES>>>(x, out);
}